// round 5
// baseline (speedup 1.0000x reference)
#include <cuda_runtime.h>
#include <cuda_bf16.h>
#include <math.h>
#include <stdint.h>

// Problem constants
#define B_  2
#define L_  2048
#define D_  1024
#define H_  16
#define HD  64
#define M_  (B_ * L_)   // 4096

// ---------------------------------------------------------------------------
// Scratch (static device globals; no dynamic allocation allowed)
// ---------------------------------------------------------------------------
__device__ float g_q[M_ * D_];
__device__ float g_k[M_ * D_];
__device__ float g_v[M_ * D_];
__device__ float g_y[M_ * D_];
__device__ __nv_bfloat16 g_xh[M_ * D_];      // split of x (later reused for y)
__device__ __nv_bfloat16 g_xl[M_ * D_];
__device__ __nv_bfloat16 g_wh[4 * D_ * D_];  // transposed split weights
__device__ __nv_bfloat16 g_wl[4 * D_ * D_];

// ---------------------------------------------------------------------------
// Helpers
// ---------------------------------------------------------------------------
__device__ __forceinline__ void mma16816(float* c,
                                         uint32_t a0, uint32_t a1,
                                         uint32_t a2, uint32_t a3,
                                         uint32_t b0, uint32_t b1)
{
    asm volatile(
        "mma.sync.aligned.m16n8k16.row.col.f32.bf16.bf16.f32 "
        "{%0,%1,%2,%3}, {%4,%5,%6,%7}, {%8,%9}, {%0,%1,%2,%3};"
        : "+f"(c[0]), "+f"(c[1]), "+f"(c[2]), "+f"(c[3])
        : "r"(a0), "r"(a1), "r"(a2), "r"(a3), "r"(b0), "r"(b1));
}

__device__ __forceinline__ void split2(float x0, float x1,
                                       uint32_t& hi, uint32_t& lo)
{
    __nv_bfloat162 hp = __floats2bfloat162_rn(x0, x1);
    float2 hf = __bfloat1622float2(hp);
    __nv_bfloat162 lp = __floats2bfloat162_rn(x0 - hf.x, x1 - hf.y);
    hi = *(uint32_t*)&hp;
    lo = *(uint32_t*)&lp;
}

__device__ __forceinline__ uint32_t smem_u32(const void* p) {
    uint32_t a;
    asm("{ .reg .u64 t; cvta.to.shared.u64 t, %1; cvt.u32.u64 %0, t; }"
        : "=r"(a) : "l"(p));
    return a;
}

__device__ __forceinline__ void cpa16(uint32_t dst, const void* src) {
    asm volatile("cp.async.cg.shared.global [%0], [%1], 16;"
                 :: "r"(dst), "l"(src));
}
#define CP_COMMIT  asm volatile("cp.async.commit_group;")
#define CP_WAIT(n) asm volatile("cp.async.wait_group %0;" :: "n"(n))

// ---------------------------------------------------------------------------
// split_f32: elementwise split of an f32 array into bf16 hi/lo
// ---------------------------------------------------------------------------
__global__ __launch_bounds__(256) void split_f32(
    const float* __restrict__ src,
    __nv_bfloat16* __restrict__ hi, __nv_bfloat16* __restrict__ lo)
{
    int i = blockIdx.x * blockDim.x + threadIdx.x;   // float4 index
    float4 v = ((const float4*)src)[i];
    uint32_t h0, l0, h1, l1;
    split2(v.x, v.y, h0, l0);
    split2(v.z, v.w, h1, l1);
    ((uint32_t*)hi)[2 * i]     = h0;
    ((uint32_t*)hi)[2 * i + 1] = h1;
    ((uint32_t*)lo)[2 * i]     = l0;
    ((uint32_t*)lo)[2 * i + 1] = l1;
}

// ---------------------------------------------------------------------------
// splitw: transpose + split weights: g_wh[z*1024 + n][k] = bf16hi(W_z[k][n])
// ---------------------------------------------------------------------------
__global__ __launch_bounds__(256) void splitw(
    const float* __restrict__ W0, const float* __restrict__ W1,
    const float* __restrict__ W2, const float* __restrict__ W3)
{
    __shared__ float tile[32][33];
    const float* srcs[4] = {W0, W1, W2, W3};
    const float* src = srcs[blockIdx.z];

    int x = blockIdx.x * 32 + threadIdx.x;   // n
    int y = blockIdx.y * 32 + threadIdx.y;   // k
#pragma unroll
    for (int i = 0; i < 4; ++i)
        tile[threadIdx.y + i * 8][threadIdx.x] = src[(size_t)(y + i * 8) * D_ + x];
    __syncthreads();

    uint32_t* whu = (uint32_t*)g_wh;
    uint32_t* wlu = (uint32_t*)g_wl;
    int tid2 = threadIdx.y * 32 + threadIdx.x;
#pragma unroll
    for (int p = 0; p < 2; ++p) {
        int q = tid2 + p * 256;              // 0..511
        int nl = q >> 4;                     // 0..31
        int kp = q & 15;                     // k-pair 0..15
        uint32_t hi, lo;
        split2(tile[2 * kp][nl], tile[2 * kp + 1][nl], hi, lo);
        size_t o = ((size_t)(blockIdx.z * D_ + blockIdx.x * 32 + nl) * D_
                    + blockIdx.y * 32) / 2 + kp;
        whu[o] = hi;
        wlu[o] = lo;
    }
}

// ---------------------------------------------------------------------------
// gemm_pre: C = alpha * A @ B^T with pre-split bf16 hi/lo operands (3-term),
// double-buffered cp.async. CTA 128x128, K-chunk 32, 256 threads.
// Output select: sel = blockIdx.x>>3 -> Cq/Ck/Cv (QKV fused); alpha0 on sel 0.
// ---------------------------------------------------------------------------
#define PST 20                       // smem row stride in u32 (80 bytes)
#define TILE_B (128 * PST * 4)       // 10240 bytes per operand tile
#define STAGE_B (4 * TILE_B)         // 40960
#define GEMM2_SMEM (2 * STAGE_B)     // 81920

__global__ __launch_bounds__(256, 2) void gemm_pre(
    const __nv_bfloat16* __restrict__ Agh, const __nv_bfloat16* __restrict__ Agl,
    const __nv_bfloat16* __restrict__ Bgh, const __nv_bfloat16* __restrict__ Bgl,
    float* __restrict__ Cq, float* __restrict__ Ck, float* __restrict__ Cv,
    float alpha0)
{
    extern __shared__ char smp[];
    const uint32_t sb = smem_u32(smp);

    const int tid = threadIdx.x;
    const int wid = tid >> 5;
    const int lane = tid & 31;
    const int wm = wid & 1;
    const int wn = wid >> 1;
    const int g  = lane >> 2;
    const int t  = lane & 3;
    const int m0 = blockIdx.y * 128;
    const int nb = blockIdx.x;
    const int nrow0 = nb * 128;          // row into B (covers fused QKV range)
    const int sel = nb >> 3;
    float* C = (sel == 0) ? Cq : (sel == 1) ? Ck : Cv;
    const float alpha = (sel == 0) ? alpha0 : 1.0f;
    const int n0 = (nb & 7) * 128;

    float acc[4][4][4];
#pragma unroll
    for (int i = 0; i < 4; ++i)
#pragma unroll
        for (int j = 0; j < 4; ++j)
#pragma unroll
            for (int r = 0; r < 4; ++r) acc[i][j][r] = 0.0f;

    const int ldrow = tid >> 2;          // 0..63 (x2 halves -> 128 rows)
    const int ldcc  = tid & 3;           // 16B chunk within 64B row

    // stage s, K-chunk c load
    auto issue = [&](int c, int s) {
        const int k0 = c * 32;
#pragma unroll
        for (int i = 0; i < 2; ++i) {
            int row = ldrow + i * 64;
            uint32_t so = (uint32_t)(s * STAGE_B + row * 80 + ldcc * 16);
            size_t ga = (size_t)(m0 + row) * D_ + k0 + ldcc * 8;
            size_t gb = (size_t)(nrow0 + row) * D_ + k0 + ldcc * 8;
            cpa16(sb + so,              Agh + ga);
            cpa16(sb + so + TILE_B,     Agl + ga);
            cpa16(sb + so + 2 * TILE_B, Bgh + gb);
            cpa16(sb + so + 3 * TILE_B, Bgl + gb);
        }
    };

    issue(0, 0);
    CP_COMMIT;

    for (int c = 0; c < D_ / 32; ++c) {
        const int s = c & 1;
        if (c + 1 < D_ / 32) {
            issue(c + 1, s ^ 1);
            CP_COMMIT;
            CP_WAIT(1);
        } else {
            CP_WAIT(0);
        }
        __syncthreads();

        const uint32_t* Ah = (const uint32_t*)(smp + s * STAGE_B);
        const uint32_t* Al = (const uint32_t*)(smp + s * STAGE_B + TILE_B);
        const uint32_t* Bh = (const uint32_t*)(smp + s * STAGE_B + 2 * TILE_B);
        const uint32_t* Bl = (const uint32_t*)(smp + s * STAGE_B + 3 * TILE_B);

#pragma unroll
        for (int ks = 0; ks < 2; ++ks) {
            const int pc = ks * 8 + t;
            uint32_t bh[4][2], bl[4][2];
#pragma unroll
            for (int j = 0; j < 4; ++j) {
                int nr = wn * 32 + j * 8 + g;
                bh[j][0] = Bh[nr * PST + pc];
                bh[j][1] = Bh[nr * PST + pc + 4];
                bl[j][0] = Bl[nr * PST + pc];
                bl[j][1] = Bl[nr * PST + pc + 4];
            }
#pragma unroll
            for (int i = 0; i < 4; ++i) {
                int mr = wm * 64 + i * 16 + g;
                uint32_t ah0 = Ah[mr * PST + pc];
                uint32_t ah1 = Ah[(mr + 8) * PST + pc];
                uint32_t ah2 = Ah[mr * PST + pc + 4];
                uint32_t ah3 = Ah[(mr + 8) * PST + pc + 4];
                uint32_t al0 = Al[mr * PST + pc];
                uint32_t al1 = Al[(mr + 8) * PST + pc];
                uint32_t al2 = Al[mr * PST + pc + 4];
                uint32_t al3 = Al[(mr + 8) * PST + pc + 4];
#pragma unroll
                for (int j = 0; j < 4; ++j) {
                    mma16816(acc[i][j], ah0, ah1, ah2, ah3, bh[j][0], bh[j][1]);
                    mma16816(acc[i][j], al0, al1, al2, al3, bh[j][0], bh[j][1]);
                    mma16816(acc[i][j], ah0, ah1, ah2, ah3, bl[j][0], bl[j][1]);
                }
            }
        }
        __syncthreads();
    }

#pragma unroll
    for (int i = 0; i < 4; ++i) {
        int row = m0 + wm * 64 + i * 16 + g;
#pragma unroll
        for (int j = 0; j < 4; ++j) {
            int col = n0 + wn * 32 + j * 8 + t * 2;
            float2 o0 = make_float2(alpha * acc[i][j][0], alpha * acc[i][j][1]);
            float2 o1 = make_float2(alpha * acc[i][j][2], alpha * acc[i][j][3]);
            *(float2*)(C + (size_t)row * D_ + col)       = o0;
            *(float2*)(C + (size_t)(row + 8) * D_ + col) = o1;
        }
    }
}

// ---------------------------------------------------------------------------
// RoPE applied in-place to q and k
// ---------------------------------------------------------------------------
__global__ __launch_bounds__(256) void rope_kernel(float* __restrict__ q,
                                                   float* __restrict__ k)
{
    int idx = blockIdx.x * blockDim.x + threadIdx.x;
    int row = idx >> 9;
    int c   = idx & 511;
    int h   = c >> 5;
    int i   = c & 31;
    int pos = row & (L_ - 1);

    float freq = exp2f(-13.287712379549449f * (float)(2 * i) * (1.0f / 64.0f));
    float ang  = (float)pos * freq;
    float s, cc;
    sincosf(ang, &s, &cc);

    int base = row * D_ + h * HD + 2 * i;
    float q0 = q[base], q1 = q[base + 1];
    q[base]     = q0 * cc - q1 * s;
    q[base + 1] = q1 * cc + q0 * s;
    float k0 = k[base], k1 = k[base + 1];
    k[base]     = k0 * cc - k1 * s;
    k[base + 1] = k1 * cc + k0 * s;
}

// ---------------------------------------------------------------------------
// Tensor-core flash attention (proven R4 kernel, unchanged)
// ---------------------------------------------------------------------------
#define FST 36

__global__ __launch_bounds__(256, 2) void flash_mma(
    const float* __restrict__ q, const float* __restrict__ k,
    const float* __restrict__ v, float* __restrict__ o)
{
    __shared__ uint32_t Khi[64 * FST], Klo[64 * FST];
    __shared__ uint32_t Vhi[64 * FST], Vlo[64 * FST];

    const int tid  = threadIdx.x;
    const int wid  = tid >> 5;
    const int lane = tid & 31;
    const int g = lane >> 2;
    const int t = lane & 3;
    const int q0 = blockIdx.x * 128;
    const int h  = blockIdx.y;
    const int b  = blockIdx.z;

    const float* kb = k + (size_t)b * L_ * D_ + h * HD;
    const float* vb = v + (size_t)b * L_ * D_ + h * HD;

    uint32_t qh[4][4], ql[4][4];
    {
        const float* qrow0 = q + ((size_t)b * L_ + q0 + wid * 16 + g) * D_ + h * HD;
        const float* qrow1 = qrow0 + 8 * D_;
#pragma unroll
        for (int ks = 0; ks < 4; ++ks) {
            float2 x0 = *(const float2*)(qrow0 + ks * 16 + 2 * t);
            float2 x1 = *(const float2*)(qrow1 + ks * 16 + 2 * t);
            float2 x2 = *(const float2*)(qrow0 + ks * 16 + 2 * t + 8);
            float2 x3 = *(const float2*)(qrow1 + ks * 16 + 2 * t + 8);
            split2(x0.x, x0.y, qh[ks][0], ql[ks][0]);
            split2(x1.x, x1.y, qh[ks][1], ql[ks][1]);
            split2(x2.x, x2.y, qh[ks][2], ql[ks][2]);
            split2(x3.x, x3.y, qh[ks][3], ql[ks][3]);
        }
    }

    float acc[8][4];
#pragma unroll
    for (int j = 0; j < 8; ++j)
#pragma unroll
        for (int r = 0; r < 4; ++r) acc[j][r] = 0.0f;
    float m0r = -1e30f, m1r = -1e30f, l0r = 0.0f, l1r = 0.0f;

    for (int tile = 0; tile < L_ / 64; ++tile) {
        __syncthreads();
        const float* kt = kb + (size_t)tile * 64 * D_;
#pragma unroll
        for (int i = 0; i < 4; ++i) {
            int idx = tid + i * 256;
            int key = idx >> 4;
            int c4  = idx & 15;
            float4 x = *(const float4*)(kt + (size_t)key * D_ + c4 * 4);
            uint32_t h0, l0, h1, l1;
            split2(x.x, x.y, h0, l0);
            split2(x.z, x.w, h1, l1);
            Khi[key * FST + c4 * 2]     = h0;
            Khi[key * FST + c4 * 2 + 1] = h1;
            Klo[key * FST + c4 * 2]     = l0;
            Klo[key * FST + c4 * 2 + 1] = l1;
        }
        const float* vt = vb + (size_t)tile * 64 * D_;
#pragma unroll
        for (int i = 0; i < 2; ++i) {
            int idx = tid + i * 256;
            int c4 = idx & 15;
            int kp = idx >> 4;
            float4 v0 = *(const float4*)(vt + (size_t)(2 * kp) * D_ + c4 * 4);
            float4 v1 = *(const float4*)(vt + (size_t)(2 * kp + 1) * D_ + c4 * 4);
            const float* p0 = (const float*)&v0;
            const float* p1 = (const float*)&v1;
#pragma unroll
            for (int cc = 0; cc < 4; ++cc) {
                uint32_t hi, lo;
                split2(p0[cc], p1[cc], hi, lo);
                Vhi[(c4 * 4 + cc) * FST + kp] = hi;
                Vlo[(c4 * 4 + cc) * FST + kp] = lo;
            }
        }
        __syncthreads();

        float S[8][4];
#pragma unroll
        for (int j = 0; j < 8; ++j)
#pragma unroll
            for (int r = 0; r < 4; ++r) S[j][r] = 0.0f;
#pragma unroll
        for (int j = 0; j < 8; ++j) {
            const int nr = j * 8 + g;
#pragma unroll
            for (int ks = 0; ks < 4; ++ks) {
                uint32_t bh0 = Khi[nr * FST + ks * 8 + t];
                uint32_t bh1 = Khi[nr * FST + ks * 8 + t + 4];
                uint32_t bl0 = Klo[nr * FST + ks * 8 + t];
                uint32_t bl1 = Klo[nr * FST + ks * 8 + t + 4];
                mma16816(S[j], qh[ks][0], qh[ks][1], qh[ks][2], qh[ks][3], bh0, bh1);
                mma16816(S[j], ql[ks][0], ql[ks][1], ql[ks][2], ql[ks][3], bh0, bh1);
                mma16816(S[j], qh[ks][0], qh[ks][1], qh[ks][2], qh[ks][3], bl0, bl1);
            }
        }

        float mx0 = -1e30f, mx1 = -1e30f;
#pragma unroll
        for (int j = 0; j < 8; ++j) {
            mx0 = fmaxf(mx0, fmaxf(S[j][0], S[j][1]));
            mx1 = fmaxf(mx1, fmaxf(S[j][2], S[j][3]));
        }
        mx0 = fmaxf(mx0, __shfl_xor_sync(0xffffffffu, mx0, 1));
        mx0 = fmaxf(mx0, __shfl_xor_sync(0xffffffffu, mx0, 2));
        mx1 = fmaxf(mx1, __shfl_xor_sync(0xffffffffu, mx1, 1));
        mx1 = fmaxf(mx1, __shfl_xor_sync(0xffffffffu, mx1, 2));

        float mn0 = fmaxf(m0r, mx0);
        float mn1 = fmaxf(m1r, mx1);
        float cr0 = __expf(m0r - mn0);
        float cr1 = __expf(m1r - mn1);
        m0r = mn0; m1r = mn1;

        float sum0 = 0.0f, sum1 = 0.0f;
#pragma unroll
        for (int j = 0; j < 8; ++j) {
            S[j][0] = __expf(S[j][0] - mn0);
            S[j][1] = __expf(S[j][1] - mn0);
            S[j][2] = __expf(S[j][2] - mn1);
            S[j][3] = __expf(S[j][3] - mn1);
            sum0 += S[j][0] + S[j][1];
            sum1 += S[j][2] + S[j][3];
        }
        sum0 += __shfl_xor_sync(0xffffffffu, sum0, 1);
        sum0 += __shfl_xor_sync(0xffffffffu, sum0, 2);
        sum1 += __shfl_xor_sync(0xffffffffu, sum1, 1);
        sum1 += __shfl_xor_sync(0xffffffffu, sum1, 2);
        l0r = l0r * cr0 + sum0;
        l1r = l1r * cr1 + sum1;
#pragma unroll
        for (int j = 0; j < 8; ++j) {
            acc[j][0] *= cr0;
            acc[j][1] *= cr0;
            acc[j][2] *= cr1;
            acc[j][3] *= cr1;
        }

#pragma unroll
        for (int kb2 = 0; kb2 < 4; ++kb2) {
            uint32_t ph[4], pl[4];
            split2(S[2 * kb2][0],     S[2 * kb2][1],     ph[0], pl[0]);
            split2(S[2 * kb2][2],     S[2 * kb2][3],     ph[1], pl[1]);
            split2(S[2 * kb2 + 1][0], S[2 * kb2 + 1][1], ph[2], pl[2]);
            split2(S[2 * kb2 + 1][2], S[2 * kb2 + 1][3], ph[3], pl[3]);
#pragma unroll
            for (int j = 0; j < 8; ++j) {
                const int vr = j * 8 + g;
                uint32_t bh0 = Vhi[vr * FST + kb2 * 8 + t];
                uint32_t bh1 = Vhi[vr * FST + kb2 * 8 + t + 4];
                uint32_t bl0 = Vlo[vr * FST + kb2 * 8 + t];
                uint32_t bl1 = Vlo[vr * FST + kb2 * 8 + t + 4];
                mma16816(acc[j], ph[0], ph[1], ph[2], ph[3], bh0, bh1);
                mma16816(acc[j], pl[0], pl[1], pl[2], pl[3], bh0, bh1);
                mma16816(acc[j], ph[0], ph[1], ph[2], ph[3], bl0, bl1);
            }
        }
    }

    float inv0 = 1.0f / l0r;
    float inv1 = 1.0f / l1r;
    int row0 = q0 + wid * 16 + g;
    float* ob = o + ((size_t)b * L_ + row0) * D_ + h * HD;
#pragma unroll
    for (int j = 0; j < 8; ++j) {
        float2 o0 = make_float2(acc[j][0] * inv0, acc[j][1] * inv0);
        float2 o1 = make_float2(acc[j][2] * inv1, acc[j][3] * inv1);
        *(float2*)(ob + j * 8 + 2 * t)          = o0;
        *(float2*)(ob + 8 * D_ + j * 8 + 2 * t) = o1;
    }
}

// ---------------------------------------------------------------------------
// Host launcher
// ---------------------------------------------------------------------------
extern "C" void kernel_launch(void* const* d_in, const int* in_sizes, int n_in,
                              void* d_out, int out_size)
{
    const float* x  = (const float*)d_in[0];
    const float* Wq = (const float*)d_in[1];
    const float* Wk = (const float*)d_in[2];
    const float* Wv = (const float*)d_in[3];
    const float* Wo = (const float*)d_in[4];
    float* out = (float*)d_out;

    float *qp, *kp, *vp, *yp;
    __nv_bfloat16 *xh, *xl, *wh, *wl;
    cudaGetSymbolAddress((void**)&qp, g_q);
    cudaGetSymbolAddress((void**)&kp, g_k);
    cudaGetSymbolAddress((void**)&vp, g_v);
    cudaGetSymbolAddress((void**)&yp, g_y);
    cudaGetSymbolAddress((void**)&xh, g_xh);
    cudaGetSymbolAddress((void**)&xl, g_xl);
    cudaGetSymbolAddress((void**)&wh, g_wh);
    cudaGetSymbolAddress((void**)&wl, g_wl);

    // 1. Transpose+split weights; split x
    splitw<<<dim3(D_ / 32, D_ / 32, 4), dim3(32, 8)>>>(Wq, Wk, Wv, Wo);
    split_f32<<<(M_ * D_ / 4) / 256, 256>>>(x, xh, xl);

    // 2. Fused QKV projection (tensor-core, pre-split, cp.async pipelined)
    cudaFuncSetAttribute(gemm_pre,
                         cudaFuncAttributeMaxDynamicSharedMemorySize, GEMM2_SMEM);
    const float qscale = 1.0f / 32.0f;
    gemm_pre<<<dim3(24, M_ / 128), 256, GEMM2_SMEM>>>(
        xh, xl, wh, wl, qp, kp, vp, qscale);

    // 3. RoPE
    rope_kernel<<<(M_ * (D_ / 2)) / 256, 256>>>(qp, kp);

    // 4. Tensor-core flash attention
    dim3 fgrid(L_ / 128, H_, B_);
    flash_mma<<<fgrid, 256>>>(qp, kp, vp, yp);

    // 5. Split y (reuse xh/xl), then output projection
    split_f32<<<(M_ * D_ / 4) / 256, 256>>>(yp, xh, xl);
    gemm_pre<<<dim3(8, M_ / 128), 256, GEMM2_SMEM>>>(
        xh, xl, wh + 3 * D_ * D_, wl + 3 * D_ * D_, out, out, out, 1.0f);
}